// round 13
// baseline (speedup 1.0000x reference)
#include <cuda_runtime.h>
#include <cuda_bf16.h>
#include <cuda_fp16.h>
#include <cstdint>

// Problem constants (verified against reference setup_inputs)
#define NN 100000
#define NE 1600000
#define D1 1024
#define D2 512
#define D3 128

// ---------------- scratch (static __device__) ----------------
__device__ __half g_xw1h[(size_t)NN * D2];          // node_attr @ W1 (fp16)
__device__ __nv_bfloat16 g_h1hi[(size_t)NN * D2];   // relu(gcn1) bf16 hi
__device__ __nv_bfloat16 g_h1lo[(size_t)NN * D2];   // relu(gcn1) bf16 lo
__device__ __half g_xw2h[(size_t)NN * D3];          // h1 @ W2 (fp16)
__device__ float g_deg1[NN];
__device__ float g_dinv1[NN];
__device__ float g_dinv2[NN];
__device__ float g_ssrc[NN];
__device__ float g_sdst[NN];
__device__ int   g_counts[NN];
__device__ int   g_rowptr[NN + 1];
__device__ int   g_cursor[NN];
__device__ int   g_csr_src[NE];
__device__ float g_csr_w[NE];
__device__ int   g_is64;
// pre-converted weights (bf16 hi/lo split), layout [K][N]
__device__ __nv_bfloat16 g_w1hi[D1 * D2];
__device__ __nv_bfloat16 g_w1lo[D1 * D2];
__device__ __nv_bfloat16 g_w2hi[D2 * D3];
__device__ __nv_bfloat16 g_w2lo[D2 * D3];

// ---------------- edge_index dtype detection ----------------
__global__ void detect_kernel(const int* __restrict__ ei32) {
    unsigned lane = threadIdx.x;
    int v = ei32[2 * lane + 1];
    unsigned b = __ballot_sync(0xffffffffu, v == 0);
    if (lane == 0) g_is64 = (b == 0xffffffffu) ? 1 : 0;
}
__device__ __forceinline__ int load_idx(const int* ei32, size_t pos, int n) {
    int v;
    if (g_is64) v = (int)((const long long*)ei32)[pos];
    else        v = ei32[pos];
    return min(max(v, 0), n - 1);
}

// ---------------- weight pre-conversion ----------------
__global__ void wconv1_kernel(const float* __restrict__ W) {
    int i = blockIdx.x * blockDim.x + threadIdx.x;
    if (i < D1 * D2) {
        float x = W[i];
        __nv_bfloat16 h = __float2bfloat16(x);
        g_w1hi[i] = h;
        g_w1lo[i] = __float2bfloat16(x - __bfloat162float(h));
    }
}
__global__ void wconv2_kernel(const float* __restrict__ W) {
    int i = blockIdx.x * blockDim.x + threadIdx.x;
    if (i < D2 * D3) {
        float x = W[i];
        __nv_bfloat16 h = __float2bfloat16(x);
        g_w2hi[i] = h;
        g_w2lo[i] = __float2bfloat16(x - __bfloat162float(h));
    }
}

// ---------------- CSR construction ----------------
__global__ void init_nodes_kernel(int n) {
    int i = blockIdx.x * blockDim.x + threadIdx.x;
    if (i < n) { g_deg1[i] = 1.0f; g_counts[i] = 0; }
}
__global__ void edge_count_kernel(const int* __restrict__ ei,
                                  const float* __restrict__ ew, int E, int n) {
    int e = blockIdx.x * blockDim.x + threadIdx.x;
    if (e >= E) return;
    int col = load_idx(ei, (size_t)E + e, n);
    atomicAdd(&g_counts[col], 1);
    atomicAdd(&g_deg1[col], ew[e]);
}
__global__ void dinv1_kernel(int n) {
    int i = blockIdx.x * blockDim.x + threadIdx.x;
    if (i < n) {
        float d = g_deg1[i];
        g_dinv1[i] = (d > 0.0f) ? rsqrtf(d) : 0.0f;
    }
}
__global__ void scan_kernel(int n) {
    __shared__ int wsum[32];
    __shared__ int s_carry;
    const int tid = threadIdx.x, lane = tid & 31, warp = tid >> 5;
    if (tid == 0) s_carry = 0;
    __syncthreads();
    for (int base = 0; base < n; base += 1024) {
        int i = base + tid;
        int v = (i < n) ? g_counts[i] : 0;
        int incl = v;
        #pragma unroll
        for (int o = 1; o < 32; o <<= 1) {
            int t = __shfl_up_sync(0xffffffffu, incl, o);
            if (lane >= o) incl += t;
        }
        if (lane == 31) wsum[warp] = incl;
        __syncthreads();
        if (warp == 0) {
            int s = wsum[lane];
            #pragma unroll
            for (int o = 1; o < 32; o <<= 1) {
                int t = __shfl_up_sync(0xffffffffu, s, o);
                if (lane >= o) s += t;
            }
            wsum[lane] = s;
        }
        __syncthreads();
        int excl = s_carry + (warp ? wsum[warp - 1] : 0) + incl - v;
        if (i < n) { g_rowptr[i] = excl; g_cursor[i] = excl; }
        int total = wsum[31];
        __syncthreads();
        if (tid == 0) s_carry += total;
        __syncthreads();
    }
    if (tid == 0) g_rowptr[n] = s_carry;
}
__global__ void fill_kernel(const int* __restrict__ ei,
                            const float* __restrict__ ew, int E, int n) {
    int e = blockIdx.x * blockDim.x + threadIdx.x;
    if (e >= E) return;
    int row = load_idx(ei, (size_t)e, n);
    int col = load_idx(ei, (size_t)E + e, n);
    int pos = atomicAdd(&g_cursor[col], 1);
    g_csr_src[pos] = row;
    g_csr_w[pos]   = ew[e] * g_dinv1[row];
}

// ---------------- common MMA helpers ----------------
__device__ __forceinline__ uint32_t sptr(const void* p) {
    return (uint32_t)__cvta_generic_to_shared(p);
}
__device__ __forceinline__ void ldsm_x4(uint32_t& r0, uint32_t& r1, uint32_t& r2,
                                        uint32_t& r3, uint32_t addr) {
    asm volatile("ldmatrix.sync.aligned.m8n8.x4.shared.b16 {%0,%1,%2,%3}, [%4];"
                 : "=r"(r0), "=r"(r1), "=r"(r2), "=r"(r3) : "r"(addr));
}
__device__ __forceinline__ void ldsm_x2t(uint32_t& r0, uint32_t& r1, uint32_t addr) {
    asm volatile("ldmatrix.sync.aligned.m8n8.x2.trans.shared.b16 {%0,%1}, [%2];"
                 : "=r"(r0), "=r"(r1) : "r"(addr));
}
__device__ __forceinline__ void mma_bf16(float* c, const uint32_t* a, const uint32_t* b) {
    asm volatile("mma.sync.aligned.m16n8k16.row.col.f32.bf16.bf16.f32 "
                 "{%0,%1,%2,%3}, {%4,%5,%6,%7}, {%8,%9}, {%0,%1,%2,%3};"
                 : "+f"(c[0]), "+f"(c[1]), "+f"(c[2]), "+f"(c[3])
                 : "r"(a[0]), "r"(a[1]), "r"(a[2]), "r"(a[3]),
                   "r"(b[0]), "r"(b[1]));
}
__device__ __forceinline__ void split2(float x, float y, __nv_bfloat162& hi, __nv_bfloat162& lo) {
    __nv_bfloat16 hx = __float2bfloat16(x);
    __nv_bfloat16 hy = __float2bfloat16(y);
    __nv_bfloat16 lx = __float2bfloat16(x - __bfloat162float(hx));
    __nv_bfloat16 ly = __float2bfloat16(y - __bfloat162float(hy));
    hi = __halves2bfloat162(hx, hy);
    lo = __halves2bfloat162(lx, ly);
}

// ---------------- GEMM1: BM=64, BN=256, BK=32, 256 threads, warp tile 32x64 ----------------
// C[M,512] fp16 = A[M,1024] fp32 @ W1 (pre-split bf16 hi/lo), 3-term split accumulate.
#define G1_AS_BYTES (2 * 2 * 64 * 40 * 2)      // 20480
#define G1_BS_BYTES (2 * 2 * 32 * 264 * 2)     // 67584
#define G1_SMEM (G1_AS_BYTES + G1_BS_BYTES)    // 88064

__global__ void __launch_bounds__(256, 1)
bfgemm1_kernel(const float* __restrict__ A, int M) {
    extern __shared__ __align__(16) char dyn_smem[];
    typedef __nv_bfloat16 (*As1T)[2][64][40];
    typedef __nv_bfloat16 (*Bs1T)[2][32][264];
    As1T As = (As1T)dyn_smem;
    Bs1T Bs = (Bs1T)(dyn_smem + G1_AS_BYTES);

    const int t = threadIdx.x;
    const int lane = t & 31;
    const int warp = t >> 5;
    const int wm = (warp >> 2) * 32;
    const int wn = (warp & 3) * 64;
    const int m0 = blockIdx.y * 64;
    const int colTile = blockIdx.x * 256;

    const int aRow0 = t >> 2;         // 0..63
    const int aCol  = (t & 3) * 4;    // 0,4,8,12 (+16 second load)
    const int bRow0 = t >> 3;         // 0..31
    const int bColH = (t & 7) * 32;   // bf16 col base, 4 consecutive uint4

    float acc[2][8][4];
    #pragma unroll
    for (int i = 0; i < 2; i++)
        #pragma unroll
        for (int j = 0; j < 8; j++)
            #pragma unroll
            for (int q = 0; q < 4; q++) acc[i][j][q] = 0.0f;

    float4 pa[2];
    uint4  pbh[4], pbl[4];

    // prefetch k0 = 0
    {
        int gr = m0 + aRow0;
        pa[0] = make_float4(0.f, 0.f, 0.f, 0.f);
        pa[1] = make_float4(0.f, 0.f, 0.f, 0.f);
        if (gr < M) {
            pa[0] = *(const float4*)&A[(size_t)gr * D1 + aCol];
            pa[1] = *(const float4*)&A[(size_t)gr * D1 + aCol + 16];
        }
        #pragma unroll
        for (int i = 0; i < 4; i++) {
            size_t off = (size_t)bRow0 * D2 + colTile + bColH + i * 8;
            pbh[i] = *(const uint4*)&g_w1hi[off];
            pbl[i] = *(const uint4*)&g_w1lo[off];
        }
    }
    // store tile 0 into buf 0
    {
        __nv_bfloat162 h0, l0, h1, l1;
        split2(pa[0].x, pa[0].y, h0, l0); split2(pa[0].z, pa[0].w, h1, l1);
        *(__nv_bfloat162*)&As[0][0][aRow0][aCol]     = h0;
        *(__nv_bfloat162*)&As[0][0][aRow0][aCol + 2] = h1;
        *(__nv_bfloat162*)&As[0][1][aRow0][aCol]     = l0;
        *(__nv_bfloat162*)&As[0][1][aRow0][aCol + 2] = l1;
        split2(pa[1].x, pa[1].y, h0, l0); split2(pa[1].z, pa[1].w, h1, l1);
        *(__nv_bfloat162*)&As[0][0][aRow0][aCol + 16] = h0;
        *(__nv_bfloat162*)&As[0][0][aRow0][aCol + 18] = h1;
        *(__nv_bfloat162*)&As[0][1][aRow0][aCol + 16] = l0;
        *(__nv_bfloat162*)&As[0][1][aRow0][aCol + 18] = l1;
        #pragma unroll
        for (int i = 0; i < 4; i++) {
            *(uint4*)&Bs[0][0][bRow0][bColH + i * 8] = pbh[i];
            *(uint4*)&Bs[0][1][bRow0][bColH + i * 8] = pbl[i];
        }
    }
    __syncthreads();

    const int nk = D1 / 32;   // 32
    for (int it = 0; it < nk; it++) {
        const int buf = it & 1;
        if (it + 1 < nk) {
            const int kn = (it + 1) * 32;
            int gr = m0 + aRow0;
            pa[0] = make_float4(0.f, 0.f, 0.f, 0.f);
            pa[1] = make_float4(0.f, 0.f, 0.f, 0.f);
            if (gr < M) {
                pa[0] = *(const float4*)&A[(size_t)gr * D1 + kn + aCol];
                pa[1] = *(const float4*)&A[(size_t)gr * D1 + kn + aCol + 16];
            }
            #pragma unroll
            for (int i = 0; i < 4; i++) {
                size_t off = (size_t)(kn + bRow0) * D2 + colTile + bColH + i * 8;
                pbh[i] = *(const uint4*)&g_w1hi[off];
                pbl[i] = *(const uint4*)&g_w1lo[off];
            }
        }

        #pragma unroll
        for (int kk = 0; kk < 2; kk++) {
            const int kt = kk * 16;
            uint32_t ah[2][4], al[2][4], bh[8][2], bl[8][2];
            #pragma unroll
            for (int mt = 0; mt < 2; mt++) {
                int r = wm + mt * 16 + (lane & 15);
                int c = kt + ((lane >> 4) << 3);
                ldsm_x4(ah[mt][0], ah[mt][1], ah[mt][2], ah[mt][3], sptr(&As[buf][0][r][c]));
                ldsm_x4(al[mt][0], al[mt][1], al[mt][2], al[mt][3], sptr(&As[buf][1][r][c]));
            }
            #pragma unroll
            for (int nt = 0; nt < 8; nt++) {
                int r = kt + (lane & 15);
                int c = wn + nt * 8;
                ldsm_x2t(bh[nt][0], bh[nt][1], sptr(&Bs[buf][0][r][c]));
                ldsm_x2t(bl[nt][0], bl[nt][1], sptr(&Bs[buf][1][r][c]));
            }
            #pragma unroll
            for (int mt = 0; mt < 2; mt++)
                #pragma unroll
                for (int nt = 0; nt < 8; nt++) {
                    mma_bf16(acc[mt][nt], ah[mt], bh[nt]);
                    mma_bf16(acc[mt][nt], al[mt], bh[nt]);
                    mma_bf16(acc[mt][nt], ah[mt], bl[nt]);
                }
        }

        if (it + 1 < nk) {
            const int nb = buf ^ 1;
            __nv_bfloat162 h0, l0, h1, l1;
            split2(pa[0].x, pa[0].y, h0, l0); split2(pa[0].z, pa[0].w, h1, l1);
            *(__nv_bfloat162*)&As[nb][0][aRow0][aCol]     = h0;
            *(__nv_bfloat162*)&As[nb][0][aRow0][aCol + 2] = h1;
            *(__nv_bfloat162*)&As[nb][1][aRow0][aCol]     = l0;
            *(__nv_bfloat162*)&As[nb][1][aRow0][aCol + 2] = l1;
            split2(pa[1].x, pa[1].y, h0, l0); split2(pa[1].z, pa[1].w, h1, l1);
            *(__nv_bfloat162*)&As[nb][0][aRow0][aCol + 16] = h0;
            *(__nv_bfloat162*)&As[nb][0][aRow0][aCol + 18] = h1;
            *(__nv_bfloat162*)&As[nb][1][aRow0][aCol + 16] = l0;
            *(__nv_bfloat162*)&As[nb][1][aRow0][aCol + 18] = l1;
            #pragma unroll
            for (int i = 0; i < 4; i++) {
                *(uint4*)&Bs[nb][0][bRow0][bColH + i * 8] = pbh[i];
                *(uint4*)&Bs[nb][1][bRow0][bColH + i * 8] = pbl[i];
            }
            __syncthreads();
        }
    }

    // epilogue -> fp16
    const int g = lane >> 2, tig = lane & 3;
    #pragma unroll
    for (int mt = 0; mt < 2; mt++) {
        #pragma unroll
        for (int nt = 0; nt < 8; nt++) {
            int row = m0 + wm + mt * 16 + g;
            int col = colTile + wn + nt * 8 + tig * 2;
            if (row < M)
                *(__half2*)&g_xw1h[(size_t)row * D2 + col] =
                    __floats2half2_rn(acc[mt][nt][0], acc[mt][nt][1]);
            if (row + 8 < M)
                *(__half2*)&g_xw1h[(size_t)(row + 8) * D2 + col] =
                    __floats2half2_rn(acc[mt][nt][2], acc[mt][nt][3]);
        }
    }
}

// ---------------- GEMM2: both operands pre-split bf16; BM=128,BN=128,BK=32 ----------------
#define SMEM_GEMM2 (4 * 128 * 40 * 2 + 4 * 32 * 136 * 2)   // 75776

__global__ void __launch_bounds__(256, 1)
bfgemm2_kernel(int M) {
    const __nv_bfloat16* __restrict__ Ahi = &g_h1hi[0];
    const __nv_bfloat16* __restrict__ Alo = &g_h1lo[0];
    const __nv_bfloat16* __restrict__ Bhi = &g_w2hi[0];
    const __nv_bfloat16* __restrict__ Blo = &g_w2lo[0];
    __half* __restrict__ C = &g_xw2h[0];
    const int N = D3, K = D2;
    extern __shared__ __align__(16) char dyn_smem[];
    typedef __nv_bfloat16 (*AsT)[2][128][40];
    typedef __nv_bfloat16 (*BsT)[2][32][136];
    AsT As = (AsT)dyn_smem;
    BsT Bs = (BsT)(dyn_smem + 4 * 128 * 40 * 2);

    const int t = threadIdx.x;
    const int lane = t & 31;
    const int warp = t >> 5;
    const int wm = (warp >> 2) * 64;
    const int wn = (warp & 3) * 32;
    const int rowTile = blockIdx.y * 128;
    const int colTile = blockIdx.x * 128;

    const int aRow0 = t >> 1;           // 0..127
    const int aColH = (t & 1) * 16;     // halves, 2 uint4
    const int bRow0 = t >> 4;           // +i*16
    const int bCol  = (t & 15) * 8;

    float acc[4][4][4];
    #pragma unroll
    for (int i = 0; i < 4; i++)
        #pragma unroll
        for (int j = 0; j < 4; j++)
            #pragma unroll
            for (int q = 0; q < 4; q++) acc[i][j][q] = 0.0f;

    uint4 pah[2], pal[2], pbh[2], pbl[2];
    const uint4 z4 = make_uint4(0, 0, 0, 0);

    {
        int gr = rowTile + aRow0;
        pah[0] = pah[1] = pal[0] = pal[1] = z4;
        if (gr < M) {
            size_t off = (size_t)gr * K + aColH;
            pah[0] = *(const uint4*)&Ahi[off];
            pah[1] = *(const uint4*)&Ahi[off + 8];
            pal[0] = *(const uint4*)&Alo[off];
            pal[1] = *(const uint4*)&Alo[off + 8];
        }
        #pragma unroll
        for (int i = 0; i < 2; i++) {
            size_t off = (size_t)(bRow0 + i * 16) * N + colTile + bCol;
            pbh[i] = *(const uint4*)&Bhi[off];
            pbl[i] = *(const uint4*)&Blo[off];
        }
    }
    {
        *(uint4*)&As[0][0][aRow0][aColH]     = pah[0];
        *(uint4*)&As[0][0][aRow0][aColH + 8] = pah[1];
        *(uint4*)&As[0][1][aRow0][aColH]     = pal[0];
        *(uint4*)&As[0][1][aRow0][aColH + 8] = pal[1];
        #pragma unroll
        for (int i = 0; i < 2; i++) {
            int row = bRow0 + i * 16;
            *(uint4*)&Bs[0][0][row][bCol] = pbh[i];
            *(uint4*)&Bs[0][1][row][bCol] = pbl[i];
        }
    }
    __syncthreads();

    const int nk = K / 32;   // 16
    for (int it = 0; it < nk; it++) {
        const int buf = it & 1;
        if (it + 1 < nk) {
            const int kn = (it + 1) * 32;
            int gr = rowTile + aRow0;
            pah[0] = pah[1] = pal[0] = pal[1] = z4;
            if (gr < M) {
                size_t off = (size_t)gr * K + kn + aColH;
                pah[0] = *(const uint4*)&Ahi[off];
                pah[1] = *(const uint4*)&Ahi[off + 8];
                pal[0] = *(const uint4*)&Alo[off];
                pal[1] = *(const uint4*)&Alo[off + 8];
            }
            #pragma unroll
            for (int i = 0; i < 2; i++) {
                size_t off = (size_t)(kn + bRow0 + i * 16) * N + colTile + bCol;
                pbh[i] = *(const uint4*)&Bhi[off];
                pbl[i] = *(const uint4*)&Blo[off];
            }
        }

        #pragma unroll
        for (int kk = 0; kk < 2; kk++) {
            const int kt = kk * 16;
            uint32_t ah[4][4], al[4][4], bh[4][2], bl[4][2];
            #pragma unroll
            for (int mt = 0; mt < 4; mt++) {
                int r = wm + mt * 16 + (lane & 15);
                int c = kt + ((lane >> 4) << 3);
                ldsm_x4(ah[mt][0], ah[mt][1], ah[mt][2], ah[mt][3], sptr(&As[buf][0][r][c]));
                ldsm_x4(al[mt][0], al[mt][1], al[mt][2], al[mt][3], sptr(&As[buf][1][r][c]));
            }
            #pragma unroll
            for (int nt = 0; nt < 4; nt++) {
                int r = kt + (lane & 15);
                int c = wn + nt * 8;
                ldsm_x2t(bh[nt][0], bh[nt][1], sptr(&Bs[buf][0][r][c]));
                ldsm_x2t(bl[nt][0], bl[nt][1], sptr(&Bs[buf][1][r][c]));
            }
            #pragma unroll
            for (int mt = 0; mt < 4; mt++)
                #pragma unroll
                for (int nt = 0; nt < 4; nt++) {
                    mma_bf16(acc[mt][nt], ah[mt], bh[nt]);
                    mma_bf16(acc[mt][nt], al[mt], bh[nt]);
                    mma_bf16(acc[mt][nt], ah[mt], bl[nt]);
                }
        }

        if (it + 1 < nk) {
            const int nb = buf ^ 1;
            *(uint4*)&As[nb][0][aRow0][aColH]     = pah[0];
            *(uint4*)&As[nb][0][aRow0][aColH + 8] = pah[1];
            *(uint4*)&As[nb][1][aRow0][aColH]     = pal[0];
            *(uint4*)&As[nb][1][aRow0][aColH + 8] = pal[1];
            #pragma unroll
            for (int i = 0; i < 2; i++) {
                int row = bRow0 + i * 16;
                *(uint4*)&Bs[nb][0][row][bCol] = pbh[i];
                *(uint4*)&Bs[nb][1][row][bCol] = pbl[i];
            }
            __syncthreads();
        }
    }

    const int g = lane >> 2, tig = lane & 3;
    #pragma unroll
    for (int mt = 0; mt < 4; mt++) {
        #pragma unroll
        for (int nt = 0; nt < 4; nt++) {
            int row = rowTile + wm + mt * 16 + g;
            int col = colTile + wn + nt * 8 + tig * 2;
            if (row < M)
                *(__half2*)&C[(size_t)row * N + col] =
                    __floats2half2_rn(acc[mt][nt][0], acc[mt][nt][1]);
            if (row + 8 < M)
                *(__half2*)&C[(size_t)(row + 8) * N + col] =
                    __floats2half2_rn(acc[mt][nt][2], acc[mt][nt][3]);
        }
    }
}

// ---------------- layer-1 aggregation + fused similarity ----------------
__global__ void aggregate1_kernel(const float* __restrict__ b1,
                                  const float* __restrict__ Wm, int n) {
    const int j = blockIdx.x;
    const int tid = threadIdx.x;  // 128
    const int lane = tid & 31, warp = tid >> 5;
    __shared__ int   s_src[128];
    __shared__ float s_w[128];
    __shared__ float red[2][4];
    const int start = g_rowptr[j];
    const int end   = g_rowptr[j + 1];
    float4 acc = make_float4(0.f, 0.f, 0.f, 0.f);
    for (int base = start; base < end; base += 128) {
        int ne = min(128, end - base);
        __syncthreads();
        if (tid < ne) { s_src[tid] = g_csr_src[base + tid]; s_w[tid] = g_csr_w[base + tid]; }
        __syncthreads();
        for (int i = 0; i < ne; i++) {
            const uint2 raw = *(const uint2*)&g_xw1h[(size_t)s_src[i] * D2 + tid * 4];
            const float2 v01 = __half22float2(*(const __half2*)&raw.x);
            const float2 v23 = __half22float2(*(const __half2*)&raw.y);
            const float w = s_w[i];
            acc.x = fmaf(w, v01.x, acc.x);
            acc.y = fmaf(w, v01.y, acc.y);
            acc.z = fmaf(w, v23.x, acc.z);
            acc.w = fmaf(w, v23.y, acc.w);
        }
    }
    const float di  = g_dinv1[j];
    const float di2 = di * di;
    const uint2 sraw = *(const uint2*)&g_xw1h[(size_t)j * D2 + tid * 4];
    const float2 s01 = __half22float2(*(const __half2*)&sraw.x);
    const float2 s23 = __half22float2(*(const __half2*)&sraw.y);
    const float4 bb = *(const float4*)&b1[tid * 4];
    float4 o;
    o.x = fmaxf(fmaf(di, acc.x, fmaf(di2, s01.x, bb.x)), 0.f);
    o.y = fmaxf(fmaf(di, acc.y, fmaf(di2, s01.y, bb.y)), 0.f);
    o.z = fmaxf(fmaf(di, acc.z, fmaf(di2, s23.x, bb.z)), 0.f);
    o.w = fmaxf(fmaf(di, acc.w, fmaf(di2, s23.y, bb.w)), 0.f);

    // store h1 pre-split as bf16 hi/lo (feeds GEMM2 with zero in-loop conversion)
    __nv_bfloat162 h01, l01, h23, l23;
    split2(o.x, o.y, h01, l01);
    split2(o.z, o.w, h23, l23);
    size_t hidx = (size_t)j * D2 + tid * 4;
    *(uint2*)&g_h1hi[hidx] = make_uint2(*(uint32_t*)&h01, *(uint32_t*)&h23);
    *(uint2*)&g_h1lo[hidx] = make_uint2(*(uint32_t*)&l01, *(uint32_t*)&l23);

    // fused similarity projections
    const float4 wa = *(const float4*)&Wm[tid * 4];
    const float4 wb = *(const float4*)&Wm[D2 + tid * 4];
    float sa = o.x * wa.x + o.y * wa.y + o.z * wa.z + o.w * wa.w;
    float sb = o.x * wb.x + o.y * wb.y + o.z * wb.z + o.w * wb.w;
    #pragma unroll
    for (int off = 16; off; off >>= 1) {
        sa += __shfl_down_sync(0xffffffffu, sa, off);
        sb += __shfl_down_sync(0xffffffffu, sb, off);
    }
    if (lane == 0) { red[0][warp] = sa; red[1][warp] = sb; }
    __syncthreads();
    if (tid == 0) g_ssrc[j] = red[0][0] + red[0][1] + red[0][2] + red[0][3];
    if (tid == 1) g_sdst[j] = red[1][0] + red[1][1] + red[1][2] + red[1][3];
}

// ---------------- deg2 ----------------
__global__ void deg2_kernel(const float* __restrict__ bm, int n) {
    const int j = (blockIdx.x * blockDim.x + threadIdx.x) >> 5;
    const int lane = threadIdx.x & 31;
    if (j >= n) return;
    const float sd = g_sdst[j] + bm[0];
    const int start = g_rowptr[j], end = g_rowptr[j + 1];
    float sum = 0.f;
    for (int e = start + lane; e < end; e += 32) {
        sum += fmaxf(g_ssrc[g_csr_src[e]] + sd, 0.f);
    }
    #pragma unroll
    for (int o = 16; o; o >>= 1) sum += __shfl_down_sync(0xffffffffu, sum, o);
    if (lane == 0) g_dinv2[j] = rsqrtf(1.0f + sum);
}

// ---------------- layer-2 aggregation ----------------
__global__ void aggregate2_kernel(const float* __restrict__ b2,
                                  const float* __restrict__ bm,
                                  float* __restrict__ out, int n) {
    const int j = (blockIdx.x * blockDim.x + threadIdx.x) >> 5;
    const int lane = threadIdx.x & 31;
    if (j >= n) return;
    const float sd = g_sdst[j] + bm[0];
    const int start = g_rowptr[j], end = g_rowptr[j + 1];
    float4 acc = make_float4(0.f, 0.f, 0.f, 0.f);
    for (int e = start; e < end; e++) {
        int s = g_csr_src[e];
        float w = fmaxf(g_ssrc[s] + sd, 0.f) * g_dinv2[s];
        const uint2 raw = *(const uint2*)&g_xw2h[(size_t)s * D3 + lane * 4];
        const float2 v01 = __half22float2(*(const __half2*)&raw.x);
        const float2 v23 = __half22float2(*(const __half2*)&raw.y);
        acc.x = fmaf(w, v01.x, acc.x);
        acc.y = fmaf(w, v01.y, acc.y);
        acc.z = fmaf(w, v23.x, acc.z);
        acc.w = fmaf(w, v23.y, acc.w);
    }
    const float di = g_dinv2[j];
    const float di2 = di * di;
    const uint2 sraw = *(const uint2*)&g_xw2h[(size_t)j * D3 + lane * 4];
    const float2 s01 = __half22float2(*(const __half2*)&sraw.x);
    const float2 s23 = __half22float2(*(const __half2*)&sraw.y);
    const float4 bb = *(const float4*)&b2[lane * 4];
    float4 o;
    o.x = fmaf(di, acc.x, fmaf(di2, s01.x, bb.x));
    o.y = fmaf(di, acc.y, fmaf(di2, s01.y, bb.y));
    o.z = fmaf(di, acc.z, fmaf(di2, s23.x, bb.z));
    o.w = fmaf(di, acc.w, fmaf(di2, s23.y, bb.w));
    *(float4*)&out[(size_t)j * D3 + lane * 4] = o;
}

// ---------------- launch ----------------
extern "C" void kernel_launch(void* const* d_in, const int* in_sizes, int n_in,
                              void* d_out, int out_size) {
    const float* node_attr  = (const float*)d_in[0];
    const float* edge_attr  = (const float*)d_in[1];
    const int*   edge_index = (const int*)d_in[2];
    const float* W1 = (const float*)d_in[5];
    const float* b1 = (const float*)d_in[6];
    const float* W2 = (const float*)d_in[7];
    const float* b2 = (const float*)d_in[8];
    const float* Wm = (const float*)d_in[9];
    const float* bm = (const float*)d_in[10];
    float* out = (float*)d_out;

    const int n = in_sizes[0] / D1;   // 100000
    const int E = in_sizes[1];        // 1600000

    cudaFuncSetAttribute(bfgemm1_kernel, cudaFuncAttributeMaxDynamicSharedMemorySize, G1_SMEM);
    cudaFuncSetAttribute(bfgemm2_kernel, cudaFuncAttributeMaxDynamicSharedMemorySize, SMEM_GEMM2);

    cudaStream_t s1;
    cudaStreamCreateWithFlags(&s1, cudaStreamNonBlocking);
    cudaEvent_t evFork1, evJoin1, evFork2, evJoin2;
    cudaEventCreateWithFlags(&evFork1, cudaEventDisableTiming);
    cudaEventCreateWithFlags(&evJoin1, cudaEventDisableTiming);
    cudaEventCreateWithFlags(&evFork2, cudaEventDisableTiming);
    cudaEventCreateWithFlags(&evJoin2, cudaEventDisableTiming);

    const int TB = 256;

    // main: detect(1), wconv1(2), wconv2(3), GEMM1(4)  [GEMM1 = 4th launch -> ncu target]
    detect_kernel<<<1, 32>>>(edge_index);
    cudaEventRecord(evFork1, 0);
    cudaStreamWaitEvent(s1, evFork1, 0);

    wconv1_kernel<<<(D1 * D2 + TB - 1) / TB, TB>>>(W1);
    wconv2_kernel<<<(D2 * D3 + TB - 1) / TB, TB>>>(W2);
    {
        dim3 grid(D2 / 256, (n + 63) / 64);
        bfgemm1_kernel<<<grid, 256, G1_SMEM>>>(node_attr, n);
    }

    // s1: CSR chain, concurrent with GEMM1
    init_nodes_kernel<<<(n + TB - 1) / TB, TB, 0, s1>>>(n);
    edge_count_kernel<<<(E + TB - 1) / TB, TB, 0, s1>>>(edge_index, edge_attr, E, n);
    dinv1_kernel<<<(n + TB - 1) / TB, TB, 0, s1>>>(n);
    scan_kernel<<<1, 1024, 0, s1>>>(n);
    fill_kernel<<<(E + TB - 1) / TB, TB, 0, s1>>>(edge_index, edge_attr, E, n);
    cudaEventRecord(evJoin1, s1);

    // join: aggregate1 needs GEMM1 + CSR
    cudaStreamWaitEvent(0, evJoin1, 0);
    aggregate1_kernel<<<n, 128>>>(b1, Wm, n);

    // fork 2: deg2 on s1 concurrent with GEMM2
    cudaEventRecord(evFork2, 0);
    cudaStreamWaitEvent(s1, evFork2, 0);
    deg2_kernel<<<(n * 32 + TB - 1) / TB, TB, 0, s1>>>(bm, n);
    cudaEventRecord(evJoin2, s1);

    {
        dim3 grid(D3 / 128, (n + 127) / 128);
        bfgemm2_kernel<<<grid, 256, SMEM_GEMM2>>>(n);
    }
    cudaStreamWaitEvent(0, evJoin2, 0);
    aggregate2_kernel<<<(n * 32 + TB - 1) / TB, TB>>>(b2, bm, out, n);
}

// round 17
// speedup vs baseline: 1.3213x; 1.3213x over previous
#include <cuda_runtime.h>
#include <cuda_bf16.h>
#include <cuda_fp16.h>
#include <cstdint>

// Problem constants (verified against reference setup_inputs)
#define NN 100000
#define NE 1600000
#define D1 1024
#define D2 512
#define D3 128

// ---------------- scratch (static __device__) ----------------
__device__ __half g_xw1h[(size_t)NN * D2];          // node_attr @ W1 (fp16)
__device__ __nv_bfloat16 g_h1hi[(size_t)NN * D2];   // relu(gcn1) bf16 hi
__device__ __nv_bfloat16 g_h1lo[(size_t)NN * D2];   // relu(gcn1) bf16 lo
__device__ __half g_xw2h[(size_t)NN * D3];          // h1 @ W2 (fp16)
__device__ float g_deg1[NN];
__device__ float g_dinv1[NN];
__device__ float g_dinv2[NN];
__device__ float g_ssrc[NN];
__device__ float g_sdst[NN];
__device__ int   g_counts[NN];
__device__ int   g_rowptr[NN + 1];
__device__ int   g_cursor[NN];
__device__ int   g_csr_src[NE];
__device__ float g_csr_w[NE];
__device__ int   g_is64;
// pre-converted weights (bf16 hi/lo split), layout [K][N]
__device__ __nv_bfloat16 g_w1hi[D1 * D2];
__device__ __nv_bfloat16 g_w1lo[D1 * D2];
__device__ __nv_bfloat16 g_w2hi[D2 * D3];
__device__ __nv_bfloat16 g_w2lo[D2 * D3];

// ---------------- edge_index dtype detection ----------------
__global__ void detect_kernel(const int* __restrict__ ei32) {
    unsigned lane = threadIdx.x;
    int v = ei32[2 * lane + 1];
    unsigned b = __ballot_sync(0xffffffffu, v == 0);
    if (lane == 0) g_is64 = (b == 0xffffffffu) ? 1 : 0;
}
__device__ __forceinline__ int load_idx(const int* ei32, size_t pos, int n) {
    int v;
    if (g_is64) v = (int)((const long long*)ei32)[pos];
    else        v = ei32[pos];
    return min(max(v, 0), n - 1);
}

// ---------------- weight pre-conversion ----------------
__global__ void wconv1_kernel(const float* __restrict__ W) {
    int i = blockIdx.x * blockDim.x + threadIdx.x;
    if (i < D1 * D2) {
        float x = W[i];
        __nv_bfloat16 h = __float2bfloat16(x);
        g_w1hi[i] = h;
        g_w1lo[i] = __float2bfloat16(x - __bfloat162float(h));
    }
}
__global__ void wconv2_kernel(const float* __restrict__ W) {
    int i = blockIdx.x * blockDim.x + threadIdx.x;
    if (i < D2 * D3) {
        float x = W[i];
        __nv_bfloat16 h = __float2bfloat16(x);
        g_w2hi[i] = h;
        g_w2lo[i] = __float2bfloat16(x - __bfloat162float(h));
    }
}

// ---------------- CSR construction ----------------
__global__ void init_nodes_kernel(int n) {
    int i = blockIdx.x * blockDim.x + threadIdx.x;
    if (i < n) { g_deg1[i] = 1.0f; g_counts[i] = 0; }
}
__global__ void edge_count_kernel(const int* __restrict__ ei,
                                  const float* __restrict__ ew, int E, int n) {
    int e = blockIdx.x * blockDim.x + threadIdx.x;
    if (e >= E) return;
    int col = load_idx(ei, (size_t)E + e, n);
    atomicAdd(&g_counts[col], 1);
    atomicAdd(&g_deg1[col], ew[e]);
}
__global__ void dinv1_kernel(int n) {
    int i = blockIdx.x * blockDim.x + threadIdx.x;
    if (i < n) {
        float d = g_deg1[i];
        g_dinv1[i] = (d > 0.0f) ? rsqrtf(d) : 0.0f;
    }
}
__global__ void scan_kernel(int n) {
    __shared__ int wsum[32];
    __shared__ int s_carry;
    const int tid = threadIdx.x, lane = tid & 31, warp = tid >> 5;
    if (tid == 0) s_carry = 0;
    __syncthreads();
    for (int base = 0; base < n; base += 1024) {
        int i = base + tid;
        int v = (i < n) ? g_counts[i] : 0;
        int incl = v;
        #pragma unroll
        for (int o = 1; o < 32; o <<= 1) {
            int t = __shfl_up_sync(0xffffffffu, incl, o);
            if (lane >= o) incl += t;
        }
        if (lane == 31) wsum[warp] = incl;
        __syncthreads();
        if (warp == 0) {
            int s = wsum[lane];
            #pragma unroll
            for (int o = 1; o < 32; o <<= 1) {
                int t = __shfl_up_sync(0xffffffffu, s, o);
                if (lane >= o) s += t;
            }
            wsum[lane] = s;
        }
        __syncthreads();
        int excl = s_carry + (warp ? wsum[warp - 1] : 0) + incl - v;
        if (i < n) { g_rowptr[i] = excl; g_cursor[i] = excl; }
        int total = wsum[31];
        __syncthreads();
        if (tid == 0) s_carry += total;
        __syncthreads();
    }
    if (tid == 0) g_rowptr[n] = s_carry;
}
__global__ void fill_kernel(const int* __restrict__ ei,
                            const float* __restrict__ ew, int E, int n) {
    int e = blockIdx.x * blockDim.x + threadIdx.x;
    if (e >= E) return;
    int row = load_idx(ei, (size_t)e, n);
    int col = load_idx(ei, (size_t)E + e, n);
    int pos = atomicAdd(&g_cursor[col], 1);
    g_csr_src[pos] = row;
    g_csr_w[pos]   = ew[e] * g_dinv1[row];
}

// ---------------- common MMA helpers ----------------
__device__ __forceinline__ uint32_t sptr(const void* p) {
    return (uint32_t)__cvta_generic_to_shared(p);
}
__device__ __forceinline__ void ldsm_x4(uint32_t& r0, uint32_t& r1, uint32_t& r2,
                                        uint32_t& r3, uint32_t addr) {
    asm volatile("ldmatrix.sync.aligned.m8n8.x4.shared.b16 {%0,%1,%2,%3}, [%4];"
                 : "=r"(r0), "=r"(r1), "=r"(r2), "=r"(r3) : "r"(addr));
}
// x4 transposed: loads B fragments for TWO adjacent n-tiles in one op.
// lanes 0-7: rows k0-7 col n0; 8-15: rows k8-15 col n0; 16-23: k0-7 col n1; 24-31: k8-15 col n1.
__device__ __forceinline__ void ldsm_x4t(uint32_t& r0, uint32_t& r1, uint32_t& r2,
                                         uint32_t& r3, uint32_t addr) {
    asm volatile("ldmatrix.sync.aligned.m8n8.x4.trans.shared.b16 {%0,%1,%2,%3}, [%4];"
                 : "=r"(r0), "=r"(r1), "=r"(r2), "=r"(r3) : "r"(addr));
}
__device__ __forceinline__ void mma_bf16(float* c, const uint32_t* a, const uint32_t* b) {
    asm volatile("mma.sync.aligned.m16n8k16.row.col.f32.bf16.bf16.f32 "
                 "{%0,%1,%2,%3}, {%4,%5,%6,%7}, {%8,%9}, {%0,%1,%2,%3};"
                 : "+f"(c[0]), "+f"(c[1]), "+f"(c[2]), "+f"(c[3])
                 : "r"(a[0]), "r"(a[1]), "r"(a[2]), "r"(a[3]),
                   "r"(b[0]), "r"(b[1]));
}
__device__ __forceinline__ void split2(float x, float y, __nv_bfloat162& hi, __nv_bfloat162& lo) {
    __nv_bfloat16 hx = __float2bfloat16(x);
    __nv_bfloat16 hy = __float2bfloat16(y);
    __nv_bfloat16 lx = __float2bfloat16(x - __bfloat162float(hx));
    __nv_bfloat16 ly = __float2bfloat16(y - __bfloat162float(hy));
    hi = __halves2bfloat162(hx, hy);
    lo = __halves2bfloat162(lx, ly);
}

#define SMEM_GEMM_BYTES (4 * 128 * 40 * 2 + 4 * 32 * 136 * 2)   // 75776

// ---------------- GEMM1: 128x128x32, A fp32 (split in-kernel), B pre-split ----------------
__global__ void __launch_bounds__(256, 1)
bfgemm1_kernel(const float* __restrict__ A, int M) {
    const __nv_bfloat16* __restrict__ Bhi = &g_w1hi[0];
    const __nv_bfloat16* __restrict__ Blo = &g_w1lo[0];
    __half* __restrict__ C = &g_xw1h[0];
    const int N = D2, K = D1;
    extern __shared__ __align__(16) char dyn_smem[];
    typedef __nv_bfloat16 (*AsT)[2][128][40];
    typedef __nv_bfloat16 (*BsT)[2][32][136];
    AsT As = (AsT)dyn_smem;
    BsT Bs = (BsT)(dyn_smem + 4 * 128 * 40 * 2);

    const int t = threadIdx.x;
    const int lane = t & 31;
    const int warp = t >> 5;
    const int wm = (warp >> 2) * 64;
    const int wn = (warp & 3) * 32;
    const int rowTile = blockIdx.y * 128;
    const int colTile = blockIdx.x * 128;

    const int aRow0 = t >> 3;            // +i*32
    const int aCol  = (t & 7) * 4;
    const int bRow0 = t >> 4;            // +i*16
    const int bCol  = (t & 15) * 8;

    float acc[4][4][4];
    #pragma unroll
    for (int i = 0; i < 4; i++)
        #pragma unroll
        for (int j = 0; j < 4; j++)
            #pragma unroll
            for (int q = 0; q < 4; q++) acc[i][j][q] = 0.0f;

    float4 pa[4];
    uint4  pbh[2], pbl[2];

    #pragma unroll
    for (int i = 0; i < 4; i++) {
        int gr = rowTile + aRow0 + i * 32;
        pa[i] = make_float4(0.f, 0.f, 0.f, 0.f);
        if (gr < M) pa[i] = *(const float4*)&A[(size_t)gr * K + aCol];
    }
    #pragma unroll
    for (int i = 0; i < 2; i++) {
        size_t off = (size_t)(bRow0 + i * 16) * N + colTile + bCol;
        pbh[i] = *(const uint4*)&Bhi[off];
        pbl[i] = *(const uint4*)&Blo[off];
    }
    #pragma unroll
    for (int i = 0; i < 4; i++) {
        int row = aRow0 + i * 32;
        __nv_bfloat162 h0, l0, h1, l1;
        split2(pa[i].x, pa[i].y, h0, l0);
        split2(pa[i].z, pa[i].w, h1, l1);
        *(__nv_bfloat162*)&As[0][0][row][aCol]     = h0;
        *(__nv_bfloat162*)&As[0][0][row][aCol + 2] = h1;
        *(__nv_bfloat162*)&As[0][1][row][aCol]     = l0;
        *(__nv_bfloat162*)&As[0][1][row][aCol + 2] = l1;
    }
    #pragma unroll
    for (int i = 0; i < 2; i++) {
        int row = bRow0 + i * 16;
        *(uint4*)&Bs[0][0][row][bCol] = pbh[i];
        *(uint4*)&Bs[0][1][row][bCol] = pbl[i];
    }
    __syncthreads();

    const int nk = K / 32;
    for (int it = 0; it < nk; it++) {
        const int buf = it & 1;
        if (it + 1 < nk) {
            const int kn = (it + 1) * 32;
            #pragma unroll
            for (int i = 0; i < 4; i++) {
                int gr = rowTile + aRow0 + i * 32;
                pa[i] = make_float4(0.f, 0.f, 0.f, 0.f);
                if (gr < M) pa[i] = *(const float4*)&A[(size_t)gr * K + kn + aCol];
            }
            #pragma unroll
            for (int i = 0; i < 2; i++) {
                size_t off = (size_t)(kn + bRow0 + i * 16) * N + colTile + bCol;
                pbh[i] = *(const uint4*)&Bhi[off];
                pbl[i] = *(const uint4*)&Blo[off];
            }
        }

        #pragma unroll
        for (int kk = 0; kk < 2; kk++) {
            const int kt = kk * 16;
            uint32_t ah[4][4], al[4][4], bh[4][2], bl[4][2];
            #pragma unroll
            for (int mt = 0; mt < 4; mt++) {
                int r = wm + mt * 16 + (lane & 15);
                int c = kt + ((lane >> 4) << 3);
                ldsm_x4(ah[mt][0], ah[mt][1], ah[mt][2], ah[mt][3], sptr(&As[buf][0][r][c]));
                ldsm_x4(al[mt][0], al[mt][1], al[mt][2], al[mt][3], sptr(&As[buf][1][r][c]));
            }
            // B fragments: one x4t covers two adjacent n-tiles
            #pragma unroll
            for (int nt = 0; nt < 4; nt += 2) {
                int r = kt + (lane & 15);
                int c = wn + nt * 8 + ((lane >> 4) << 3);
                ldsm_x4t(bh[nt][0], bh[nt][1], bh[nt + 1][0], bh[nt + 1][1],
                         sptr(&Bs[buf][0][r][c]));
                ldsm_x4t(bl[nt][0], bl[nt][1], bl[nt + 1][0], bl[nt + 1][1],
                         sptr(&Bs[buf][1][r][c]));
            }
            #pragma unroll
            for (int mt = 0; mt < 4; mt++)
                #pragma unroll
                for (int nt = 0; nt < 4; nt++) {
                    mma_bf16(acc[mt][nt], ah[mt], bh[nt]);
                    mma_bf16(acc[mt][nt], al[mt], bh[nt]);
                    mma_bf16(acc[mt][nt], ah[mt], bl[nt]);
                }
        }

        if (it + 1 < nk) {
            const int nb = buf ^ 1;
            #pragma unroll
            for (int i = 0; i < 4; i++) {
                int row = aRow0 + i * 32;
                __nv_bfloat162 h0, l0, h1, l1;
                split2(pa[i].x, pa[i].y, h0, l0);
                split2(pa[i].z, pa[i].w, h1, l1);
                *(__nv_bfloat162*)&As[nb][0][row][aCol]     = h0;
                *(__nv_bfloat162*)&As[nb][0][row][aCol + 2] = h1;
                *(__nv_bfloat162*)&As[nb][1][row][aCol]     = l0;
                *(__nv_bfloat162*)&As[nb][1][row][aCol + 2] = l1;
            }
            #pragma unroll
            for (int i = 0; i < 2; i++) {
                int row = bRow0 + i * 16;
                *(uint4*)&Bs[nb][0][row][bCol] = pbh[i];
                *(uint4*)&Bs[nb][1][row][bCol] = pbl[i];
            }
            __syncthreads();
        }
    }

    const int g = lane >> 2, tig = lane & 3;
    #pragma unroll
    for (int mt = 0; mt < 4; mt++) {
        #pragma unroll
        for (int nt = 0; nt < 4; nt++) {
            int row = rowTile + wm + mt * 16 + g;
            int col = colTile + wn + nt * 8 + tig * 2;
            if (row < M)
                *(__half2*)&C[(size_t)row * N + col] =
                    __floats2half2_rn(acc[mt][nt][0], acc[mt][nt][1]);
            if (row + 8 < M)
                *(__half2*)&C[(size_t)(row + 8) * N + col] =
                    __floats2half2_rn(acc[mt][nt][2], acc[mt][nt][3]);
        }
    }
}

// ---------------- GEMM2: both operands pre-split bf16; 128x128x32 ----------------
__global__ void __launch_bounds__(256, 1)
bfgemm2_kernel(int M) {
    const __nv_bfloat16* __restrict__ Ahi = &g_h1hi[0];
    const __nv_bfloat16* __restrict__ Alo = &g_h1lo[0];
    const __nv_bfloat16* __restrict__ Bhi = &g_w2hi[0];
    const __nv_bfloat16* __restrict__ Blo = &g_w2lo[0];
    __half* __restrict__ C = &g_xw2h[0];
    const int N = D3, K = D2;
    extern __shared__ __align__(16) char dyn_smem[];
    typedef __nv_bfloat16 (*AsT)[2][128][40];
    typedef __nv_bfloat16 (*BsT)[2][32][136];
    AsT As = (AsT)dyn_smem;
    BsT Bs = (BsT)(dyn_smem + 4 * 128 * 40 * 2);

    const int t = threadIdx.x;
    const int lane = t & 31;
    const int warp = t >> 5;
    const int wm = (warp >> 2) * 64;
    const int wn = (warp & 3) * 32;
    const int rowTile = blockIdx.y * 128;
    const int colTile = blockIdx.x * 128;

    const int aRow0 = t >> 1;           // 0..127
    const int aColH = (t & 1) * 16;     // halves, 2 uint4
    const int bRow0 = t >> 4;           // +i*16
    const int bCol  = (t & 15) * 8;

    float acc[4][4][4];
    #pragma unroll
    for (int i = 0; i < 4; i++)
        #pragma unroll
        for (int j = 0; j < 4; j++)
            #pragma unroll
            for (int q = 0; q < 4; q++) acc[i][j][q] = 0.0f;

    uint4 pah[2], pal[2], pbh[2], pbl[2];
    const uint4 z4 = make_uint4(0, 0, 0, 0);

    {
        int gr = rowTile + aRow0;
        pah[0] = pah[1] = pal[0] = pal[1] = z4;
        if (gr < M) {
            size_t off = (size_t)gr * K + aColH;
            pah[0] = *(const uint4*)&Ahi[off];
            pah[1] = *(const uint4*)&Ahi[off + 8];
            pal[0] = *(const uint4*)&Alo[off];
            pal[1] = *(const uint4*)&Alo[off + 8];
        }
        #pragma unroll
        for (int i = 0; i < 2; i++) {
            size_t off = (size_t)(bRow0 + i * 16) * N + colTile + bCol;
            pbh[i] = *(const uint4*)&Bhi[off];
            pbl[i] = *(const uint4*)&Blo[off];
        }
    }
    {
        *(uint4*)&As[0][0][aRow0][aColH]     = pah[0];
        *(uint4*)&As[0][0][aRow0][aColH + 8] = pah[1];
        *(uint4*)&As[0][1][aRow0][aColH]     = pal[0];
        *(uint4*)&As[0][1][aRow0][aColH + 8] = pal[1];
        #pragma unroll
        for (int i = 0; i < 2; i++) {
            int row = bRow0 + i * 16;
            *(uint4*)&Bs[0][0][row][bCol] = pbh[i];
            *(uint4*)&Bs[0][1][row][bCol] = pbl[i];
        }
    }
    __syncthreads();

    const int nk = K / 32;   // 16
    for (int it = 0; it < nk; it++) {
        const int buf = it & 1;
        if (it + 1 < nk) {
            const int kn = (it + 1) * 32;
            int gr = rowTile + aRow0;
            pah[0] = pah[1] = pal[0] = pal[1] = z4;
            if (gr < M) {
                size_t off = (size_t)gr * K + kn + aColH;
                pah[0] = *(const uint4*)&Ahi[off];
                pah[1] = *(const uint4*)&Ahi[off + 8];
                pal[0] = *(const uint4*)&Alo[off];
                pal[1] = *(const uint4*)&Alo[off + 8];
            }
            #pragma unroll
            for (int i = 0; i < 2; i++) {
                size_t off = (size_t)(kn + bRow0 + i * 16) * N + colTile + bCol;
                pbh[i] = *(const uint4*)&Bhi[off];
                pbl[i] = *(const uint4*)&Blo[off];
            }
        }

        #pragma unroll
        for (int kk = 0; kk < 2; kk++) {
            const int kt = kk * 16;
            uint32_t ah[4][4], al[4][4], bh[4][2], bl[4][2];
            #pragma unroll
            for (int mt = 0; mt < 4; mt++) {
                int r = wm + mt * 16 + (lane & 15);
                int c = kt + ((lane >> 4) << 3);
                ldsm_x4(ah[mt][0], ah[mt][1], ah[mt][2], ah[mt][3], sptr(&As[buf][0][r][c]));
                ldsm_x4(al[mt][0], al[mt][1], al[mt][2], al[mt][3], sptr(&As[buf][1][r][c]));
            }
            #pragma unroll
            for (int nt = 0; nt < 4; nt += 2) {
                int r = kt + (lane & 15);
                int c = wn + nt * 8 + ((lane >> 4) << 3);
                ldsm_x4t(bh[nt][0], bh[nt][1], bh[nt + 1][0], bh[nt + 1][1],
                         sptr(&Bs[buf][0][r][c]));
                ldsm_x4t(bl[nt][0], bl[nt][1], bl[nt + 1][0], bl[nt + 1][1],
                         sptr(&Bs[buf][1][r][c]));
            }
            #pragma unroll
            for (int mt = 0; mt < 4; mt++)
                #pragma unroll
                for (int nt = 0; nt < 4; nt++) {
                    mma_bf16(acc[mt][nt], ah[mt], bh[nt]);
                    mma_bf16(acc[mt][nt], al[mt], bh[nt]);
                    mma_bf16(acc[mt][nt], ah[mt], bl[nt]);
                }
        }

        if (it + 1 < nk) {
            const int nb = buf ^ 1;
            *(uint4*)&As[nb][0][aRow0][aColH]     = pah[0];
            *(uint4*)&As[nb][0][aRow0][aColH + 8] = pah[1];
            *(uint4*)&As[nb][1][aRow0][aColH]     = pal[0];
            *(uint4*)&As[nb][1][aRow0][aColH + 8] = pal[1];
            #pragma unroll
            for (int i = 0; i < 2; i++) {
                int row = bRow0 + i * 16;
                *(uint4*)&Bs[nb][0][row][bCol] = pbh[i];
                *(uint4*)&Bs[nb][1][row][bCol] = pbl[i];
            }
            __syncthreads();
        }
    }

    const int g = lane >> 2, tig = lane & 3;
    #pragma unroll
    for (int mt = 0; mt < 4; mt++) {
        #pragma unroll
        for (int nt = 0; nt < 4; nt++) {
            int row = rowTile + wm + mt * 16 + g;
            int col = colTile + wn + nt * 8 + tig * 2;
            if (row < M)
                *(__half2*)&C[(size_t)row * N + col] =
                    __floats2half2_rn(acc[mt][nt][0], acc[mt][nt][1]);
            if (row + 8 < M)
                *(__half2*)&C[(size_t)(row + 8) * N + col] =
                    __floats2half2_rn(acc[mt][nt][2], acc[mt][nt][3]);
        }
    }
}

// ---------------- layer-1 aggregation + fused similarity ----------------
__global__ void aggregate1_kernel(const float* __restrict__ b1,
                                  const float* __restrict__ Wm, int n) {
    const int j = blockIdx.x;
    const int tid = threadIdx.x;  // 128
    const int lane = tid & 31, warp = tid >> 5;
    __shared__ int   s_src[128];
    __shared__ float s_w[128];
    __shared__ float red[2][4];
    const int start = g_rowptr[j];
    const int end   = g_rowptr[j + 1];
    float4 acc = make_float4(0.f, 0.f, 0.f, 0.f);
    for (int base = start; base < end; base += 128) {
        int ne = min(128, end - base);
        __syncthreads();
        if (tid < ne) { s_src[tid] = g_csr_src[base + tid]; s_w[tid] = g_csr_w[base + tid]; }
        __syncthreads();
        for (int i = 0; i < ne; i++) {
            const uint2 raw = *(const uint2*)&g_xw1h[(size_t)s_src[i] * D2 + tid * 4];
            const float2 v01 = __half22float2(*(const __half2*)&raw.x);
            const float2 v23 = __half22float2(*(const __half2*)&raw.y);
            const float w = s_w[i];
            acc.x = fmaf(w, v01.x, acc.x);
            acc.y = fmaf(w, v01.y, acc.y);
            acc.z = fmaf(w, v23.x, acc.z);
            acc.w = fmaf(w, v23.y, acc.w);
        }
    }
    const float di  = g_dinv1[j];
    const float di2 = di * di;
    const uint2 sraw = *(const uint2*)&g_xw1h[(size_t)j * D2 + tid * 4];
    const float2 s01 = __half22float2(*(const __half2*)&sraw.x);
    const float2 s23 = __half22float2(*(const __half2*)&sraw.y);
    const float4 bb = *(const float4*)&b1[tid * 4];
    float4 o;
    o.x = fmaxf(fmaf(di, acc.x, fmaf(di2, s01.x, bb.x)), 0.f);
    o.y = fmaxf(fmaf(di, acc.y, fmaf(di2, s01.y, bb.y)), 0.f);
    o.z = fmaxf(fmaf(di, acc.z, fmaf(di2, s23.x, bb.z)), 0.f);
    o.w = fmaxf(fmaf(di, acc.w, fmaf(di2, s23.y, bb.w)), 0.f);

    // store h1 pre-split as bf16 hi/lo (feeds GEMM2 with zero in-loop conversion)
    __nv_bfloat162 h01, l01, h23, l23;
    split2(o.x, o.y, h01, l01);
    split2(o.z, o.w, h23, l23);
    size_t hidx = (size_t)j * D2 + tid * 4;
    *(uint2*)&g_h1hi[hidx] = make_uint2(*(uint32_t*)&h01, *(uint32_t*)&h23);
    *(uint2*)&g_h1lo[hidx] = make_uint2(*(uint32_t*)&l01, *(uint32_t*)&l23);

    // fused similarity projections
    const float4 wa = *(const float4*)&Wm[tid * 4];
    const float4 wb = *(const float4*)&Wm[D2 + tid * 4];
    float sa = o.x * wa.x + o.y * wa.y + o.z * wa.z + o.w * wa.w;
    float sb = o.x * wb.x + o.y * wb.y + o.z * wb.z + o.w * wb.w;
    #pragma unroll
    for (int off = 16; off; off >>= 1) {
        sa += __shfl_down_sync(0xffffffffu, sa, off);
        sb += __shfl_down_sync(0xffffffffu, sb, off);
    }
    if (lane == 0) { red[0][warp] = sa; red[1][warp] = sb; }
    __syncthreads();
    if (tid == 0) g_ssrc[j] = red[0][0] + red[0][1] + red[0][2] + red[0][3];
    if (tid == 1) g_sdst[j] = red[1][0] + red[1][1] + red[1][2] + red[1][3];
}

// ---------------- deg2 ----------------
__global__ void deg2_kernel(const float* __restrict__ bm, int n) {
    const int j = (blockIdx.x * blockDim.x + threadIdx.x) >> 5;
    const int lane = threadIdx.x & 31;
    if (j >= n) return;
    const float sd = g_sdst[j] + bm[0];
    const int start = g_rowptr[j], end = g_rowptr[j + 1];
    float sum = 0.f;
    for (int e = start + lane; e < end; e += 32) {
        sum += fmaxf(g_ssrc[g_csr_src[e]] + sd, 0.f);
    }
    #pragma unroll
    for (int o = 16; o; o >>= 1) sum += __shfl_down_sync(0xffffffffu, sum, o);
    if (lane == 0) g_dinv2[j] = rsqrtf(1.0f + sum);
}

// ---------------- layer-2 aggregation ----------------
__global__ void aggregate2_kernel(const float* __restrict__ b2,
                                  const float* __restrict__ bm,
                                  float* __restrict__ out, int n) {
    const int j = (blockIdx.x * blockDim.x + threadIdx.x) >> 5;
    const int lane = threadIdx.x & 31;
    if (j >= n) return;
    const float sd = g_sdst[j] + bm[0];
    const int start = g_rowptr[j], end = g_rowptr[j + 1];
    float4 acc = make_float4(0.f, 0.f, 0.f, 0.f);
    for (int e = start; e < end; e++) {
        int s = g_csr_src[e];
        float w = fmaxf(g_ssrc[s] + sd, 0.f) * g_dinv2[s];
        const uint2 raw = *(const uint2*)&g_xw2h[(size_t)s * D3 + lane * 4];
        const float2 v01 = __half22float2(*(const __half2*)&raw.x);
        const float2 v23 = __half22float2(*(const __half2*)&raw.y);
        acc.x = fmaf(w, v01.x, acc.x);
        acc.y = fmaf(w, v01.y, acc.y);
        acc.z = fmaf(w, v23.x, acc.z);
        acc.w = fmaf(w, v23.y, acc.w);
    }
    const float di = g_dinv2[j];
    const float di2 = di * di;
    const uint2 sraw = *(const uint2*)&g_xw2h[(size_t)j * D3 + lane * 4];
    const float2 s01 = __half22float2(*(const __half2*)&sraw.x);
    const float2 s23 = __half22float2(*(const __half2*)&sraw.y);
    const float4 bb = *(const float4*)&b2[lane * 4];
    float4 o;
    o.x = fmaf(di, acc.x, fmaf(di2, s01.x, bb.x));
    o.y = fmaf(di, acc.y, fmaf(di2, s01.y, bb.y));
    o.z = fmaf(di, acc.z, fmaf(di2, s23.x, bb.z));
    o.w = fmaf(di, acc.w, fmaf(di2, s23.y, bb.w));
    *(float4*)&out[(size_t)j * D3 + lane * 4] = o;
}

// ---------------- launch ----------------
extern "C" void kernel_launch(void* const* d_in, const int* in_sizes, int n_in,
                              void* d_out, int out_size) {
    const float* node_attr  = (const float*)d_in[0];
    const float* edge_attr  = (const float*)d_in[1];
    const int*   edge_index = (const int*)d_in[2];
    const float* W1 = (const float*)d_in[5];
    const float* b1 = (const float*)d_in[6];
    const float* W2 = (const float*)d_in[7];
    const float* b2 = (const float*)d_in[8];
    const float* Wm = (const float*)d_in[9];
    const float* bm = (const float*)d_in[10];
    float* out = (float*)d_out;

    const int n = in_sizes[0] / D1;   // 100000
    const int E = in_sizes[1];        // 1600000

    cudaFuncSetAttribute(bfgemm1_kernel, cudaFuncAttributeMaxDynamicSharedMemorySize, SMEM_GEMM_BYTES);
    cudaFuncSetAttribute(bfgemm2_kernel, cudaFuncAttributeMaxDynamicSharedMemorySize, SMEM_GEMM_BYTES);

    cudaStream_t s1;
    cudaStreamCreateWithFlags(&s1, cudaStreamNonBlocking);
    cudaEvent_t evFork1, evJoin1, evFork2, evJoin2;
    cudaEventCreateWithFlags(&evFork1, cudaEventDisableTiming);
    cudaEventCreateWithFlags(&evJoin1, cudaEventDisableTiming);
    cudaEventCreateWithFlags(&evFork2, cudaEventDisableTiming);
    cudaEventCreateWithFlags(&evJoin2, cudaEventDisableTiming);

    const int TB = 256;

    // main: detect(1), wconv1(2), wconv2(3), GEMM1(4)  [GEMM1 = 4th launch -> ncu target]
    detect_kernel<<<1, 32>>>(edge_index);
    cudaEventRecord(evFork1, 0);
    cudaStreamWaitEvent(s1, evFork1, 0);

    wconv1_kernel<<<(D1 * D2 + TB - 1) / TB, TB>>>(W1);
    wconv2_kernel<<<(D2 * D3 + TB - 1) / TB, TB>>>(W2);
    {
        dim3 grid(D2 / 128, (n + 127) / 128);
        bfgemm1_kernel<<<grid, 256, SMEM_GEMM_BYTES>>>(node_attr, n);
    }

    // s1: CSR chain, concurrent with GEMM1
    init_nodes_kernel<<<(n + TB - 1) / TB, TB, 0, s1>>>(n);
    edge_count_kernel<<<(E + TB - 1) / TB, TB, 0, s1>>>(edge_index, edge_attr, E, n);
    dinv1_kernel<<<(n + TB - 1) / TB, TB, 0, s1>>>(n);
    scan_kernel<<<1, 1024, 0, s1>>>(n);
    fill_kernel<<<(E + TB - 1) / TB, TB, 0, s1>>>(edge_index, edge_attr, E, n);
    cudaEventRecord(evJoin1, s1);

    // join: aggregate1 needs GEMM1 + CSR
    cudaStreamWaitEvent(0, evJoin1, 0);
    aggregate1_kernel<<<n, 128>>>(b1, Wm, n);

    // fork 2: deg2 on s1 concurrent with GEMM2
    cudaEventRecord(evFork2, 0);
    cudaStreamWaitEvent(s1, evFork2, 0);
    deg2_kernel<<<(n * 32 + TB - 1) / TB, TB, 0, s1>>>(bm, n);
    cudaEventRecord(evJoin2, s1);

    {
        dim3 grid(D3 / 128, (n + 127) / 128);
        bfgemm2_kernel<<<grid, 256, SMEM_GEMM_BYTES>>>(n);
    }
    cudaStreamWaitEvent(0, evJoin2, 0);
    aggregate2_kernel<<<(n * 32 + TB - 1) / TB, TB>>>(b2, bm, out, n);
}